// round 3
// baseline (speedup 1.0000x reference)
#include <cuda_runtime.h>
#include <math.h>

// EgoCrossAttnPool: B=8, N=2048, K=32, D=128, H=4, HD=32.
// One CTA of 128 threads per BN row. FP32 with packed fma.rn.f32x2 (FFMA2)
// in all dense phases. K/V projection: accumulator pairs along K, kv tile
// stored transposed [feature][k] (stride 36, 16B-aligned rows) so k-pairs
// load as 64-bit LDS broadcast lanes; weight loads software-pipelined.
// Q/O projections packed along the i (reduction) axis. Full fp32 precision.

#define Dm   128
#define Kn   32
#define NH   4
#define HDm  32
#define PAD  129   // kh/vh row stride: conflict-free for lane=k access
#define KT   36    // transposed kv stride (floats): 36*4=144 B ≡ 0 mod 16

typedef unsigned long long u64;

__device__ __forceinline__ u64 pack2(float lo, float hi) {
    u64 r;
    asm("mov.b64 %0, {%1, %2};" : "=l"(r) : "f"(lo), "f"(hi));
    return r;
}
__device__ __forceinline__ float2 unpack2(u64 v) {
    float2 f;
    asm("mov.b64 {%0, %1}, %2;" : "=f"(f.x), "=f"(f.y) : "l"(v));
    return f;
}
__device__ __forceinline__ u64 fma2(u64 a, u64 b, u64 c) {
    u64 d;
    asm("fma.rn.f32x2 %0, %1, %2, %3;" : "=l"(d) : "l"(a), "l"(b), "l"(c));
    return d;
}

__global__ __launch_bounds__(128, 4)
void ego_attn_kernel(
    const float* __restrict__ ego_q,
    const float* __restrict__ nbr,
    const int*   __restrict__ mask,
    const float* __restrict__ lnq_s, const float* __restrict__ lnq_b,
    const float* __restrict__ lnk_s, const float* __restrict__ lnk_b,
    const float* __restrict__ Wq, const float* __restrict__ bq,
    const float* __restrict__ Wk, const float* __restrict__ bk,
    const float* __restrict__ Wv, const float* __restrict__ bv,
    const float* __restrict__ Wo, const float* __restrict__ bo,
    float* __restrict__ y)
{
    extern __shared__ float smf[];
    float* q_sh  = smf;                   // 128
    float* kv_t  = q_sh  + Dm;            // 128*36 transposed: kv_t[i*KT + k]
    float* kh_sh = kv_t + Dm * KT;        // 32*129
    float* vh_sh = kh_sh + Kn * PAD;      // 32*129
    float* qh_sh = vh_sh + Kn * PAD;      // 128
    float* o_sh  = qh_sh + Dm;            // 128

    __shared__ float red[NH];
    __shared__ int   msk[Kn];
    __shared__ int   hasany;

    const int bn   = blockIdx.x;
    const int t    = threadIdx.x;
    const int lane = t & 31;
    const int w    = t >> 5;

    // ---- mask + fallback (warp 0). Reading as int: correct for either
    //      int32- or float32-materialized bools (1.0f bits != 0). ----
    if (w == 0) {
        int mv = (mask[bn * Kn + lane] != 0);
        unsigned bal = __ballot_sync(0xffffffffu, mv);
        if (lane == 0) hasany = (bal != 0);
        msk[lane] = mv | ((lane == 0) & (bal == 0));
    }

    // ---- LayerNorm of ego_q row (block reduce over 128) ----
    float x_q = ego_q[(size_t)bn * Dm + t];
    {
        float s = x_q;
        #pragma unroll
        for (int o = 16; o; o >>= 1) s += __shfl_xor_sync(0xffffffffu, s, o);
        if (lane == 0) red[w] = s;
        __syncthreads();
        float mu = (red[0] + red[1] + red[2] + red[3]) * (1.0f / Dm);
        float dx = x_q - mu;
        float v  = dx * dx;
        __syncthreads();   // all have read red before reuse
        #pragma unroll
        for (int o = 16; o; o >>= 1) v += __shfl_xor_sync(0xffffffffu, v, o);
        if (lane == 0) red[w] = v;
        __syncthreads();
        float var = (red[0] + red[1] + red[2] + red[3]) * (1.0f / Dm);
        q_sh[t] = dx * rsqrtf(var + 1e-6f) * lnq_s[t] + lnq_b[t];
    }

    // ---- LayerNorm of kv rows into TRANSPOSED smem: warp w -> rows [8w,8w+8) ----
    {
        float s0 = lnk_s[lane],      s1 = lnk_s[lane + 32],
              s2 = lnk_s[lane + 64], s3 = lnk_s[lane + 96];
        float b0 = lnk_b[lane],      b1 = lnk_b[lane + 32],
              b2 = lnk_b[lane + 64], b3 = lnk_b[lane + 96];
        for (int r = 0; r < 8; r++) {
            int row = w * 8 + r;
            const float* p = nbr + ((size_t)bn * Kn + row) * Dm;
            float x0 = p[lane], x1 = p[lane + 32], x2 = p[lane + 64], x3 = p[lane + 96];
            float s = x0 + x1 + x2 + x3;
            #pragma unroll
            for (int o = 16; o; o >>= 1) s += __shfl_xor_sync(0xffffffffu, s, o);
            float mu = s * (1.0f / Dm);
            float d0 = x0 - mu, d1 = x1 - mu, d2 = x2 - mu, d3 = x3 - mu;
            float v = d0 * d0 + d1 * d1 + d2 * d2 + d3 * d3;
            #pragma unroll
            for (int o = 16; o; o >>= 1) v += __shfl_xor_sync(0xffffffffu, v, o);
            float rs = rsqrtf(v * (1.0f / Dm) + 1e-6f);
            // transposed stores: kv_t[feature * KT + row]
            kv_t[(lane)      * KT + row] = d0 * rs * s0 + b0;
            kv_t[(lane + 32) * KT + row] = d1 * rs * s1 + b1;
            kv_t[(lane + 64) * KT + row] = d2 * rs * s2 + b2;
            kv_t[(lane + 96) * KT + row] = d3 * rs * s3 + b3;
        }
    }
    __syncthreads();

    // ---- Q projection (FFMA2 along i): thread t computes column t ----
    {
        const float* wq = Wq + t;
        u64 acc2 = pack2(bq[t], 0.f);
        const u64* q2 = (const u64*)q_sh;   // q_sh 16B-aligned
        #pragma unroll 4
        for (int i = 0; i < Dm / 2; i++) {
            u64 w2 = pack2(wq[(2 * i) * Dm], wq[(2 * i + 1) * Dm]);
            acc2 = fma2(q2[i], w2, acc2);
        }
        float2 a = unpack2(acc2);
        qh_sh[t] = (a.x + a.y) * 0.17677669529663689f;  // (q@Wq+bq)/sqrt(32)
    }

    // ---- K & V projections: 32 packed accumulators (64 FMA lanes)/thread,
    //      weight loads software-pipelined one iteration ahead ----
    {
        u64 ak2[Kn / 2], av2[Kn / 2];
        {
            u64 bk2 = pack2(bk[t], bk[t]);
            u64 bv2 = pack2(bv[t], bv[t]);
            #pragma unroll
            for (int j = 0; j < Kn / 2; j++) { ak2[j] = bk2; av2[j] = bv2; }
        }
        const float* wkp = Wk + t;
        const float* wvp = Wv + t;
        float wk_n = wkp[0];
        float wv_n = wvp[0];
        #pragma unroll 4
        for (int i = 0; i < Dm; i++) {
            float wk = wk_n, wv = wv_n;
            if (i + 1 < Dm) {                 // prefetch next weights
                wk_n = wkp[(i + 1) * Dm];
                wv_n = wvp[(i + 1) * Dm];
            }
            u64 wk2 = pack2(wk, wk);
            u64 wv2 = pack2(wv, wv);
            const ulonglong2* xr =
                (const ulonglong2*)(kv_t + (size_t)i * KT);  // 16B aligned (KT=36)
            #pragma unroll
            for (int j = 0; j < 8; j++) {
                ulonglong2 x = xr[j];  // k = 4j..4j+3, uniform -> LDS.128 broadcast
                ak2[2 * j]     = fma2(x.x, wk2, ak2[2 * j]);
                av2[2 * j]     = fma2(x.x, wv2, av2[2 * j]);
                ak2[2 * j + 1] = fma2(x.y, wk2, ak2[2 * j + 1]);
                av2[2 * j + 1] = fma2(x.y, wv2, av2[2 * j + 1]);
            }
        }
        #pragma unroll
        for (int j = 0; j < Kn / 2; j++) {
            float2 a = unpack2(ak2[j]);
            float2 b = unpack2(av2[j]);
            kh_sh[(2 * j)     * PAD + t] = a.x;
            kh_sh[(2 * j + 1) * PAD + t] = a.y;
            vh_sh[(2 * j)     * PAD + t] = b.x;
            vh_sh[(2 * j + 1) * PAD + t] = b.y;
        }
    }
    __syncthreads();

    // ---- scores + masked softmax: warp w = head h, lane = k ----
    float attn;
    {
        const int h = w, k = lane;
        const float* qv = qh_sh + h * HDm;           // broadcast
        const float* kr = kh_sh + k * PAD + h * HDm; // conflict-free (PAD=129)
        float s = 0.f;
        #pragma unroll
        for (int d = 0; d < HDm; d++) s = fmaf(qv[d], kr[d], s);
        float sm = msk[k] ? s : -3.0e38f;
        float mx = sm;
        #pragma unroll
        for (int o = 16; o; o >>= 1) mx = fmaxf(mx, __shfl_xor_sync(0xffffffffu, mx, o));
        float e = expf(sm - mx);
        float se = e;
        #pragma unroll
        for (int o = 16; o; o >>= 1) se += __shfl_xor_sync(0xffffffffu, se, o);
        attn = e / se;
    }

    // ---- out[h][d] = sum_k attn[h][k] * vh[k][h*32+d]; thread t = h*32+d ----
    {
        const int h = w, d = lane;
        float o = 0.f;
        #pragma unroll
        for (int k = 0; k < Kn; k++) {
            float a = __shfl_sync(0xffffffffu, attn, k);
            o = fmaf(a, vh_sh[k * PAD + h * HDm + d], o);
        }
        o_sh[t] = o;
    }
    __syncthreads();

    // ---- output projection (FFMA2 along i) + has_any zeroing ----
    {
        const float* wo = Wo + t;
        u64 acc2 = pack2(bo[t], 0.f);
        const u64* o2 = (const u64*)o_sh;   // o_sh 16B-aligned
        #pragma unroll 4
        for (int i = 0; i < Dm / 2; i++) {
            u64 w2 = pack2(wo[(2 * i) * Dm], wo[(2 * i + 1) * Dm]);
            acc2 = fma2(o2[i], w2, acc2);
        }
        float2 a = unpack2(acc2);
        float acc = a.x + a.y;
        if (!hasany) acc = 0.f;
        y[(size_t)bn * Dm + t] = acc;
    }
}

extern "C" void kernel_launch(void* const* d_in, const int* in_sizes, int n_in,
                              void* d_out, int out_size)
{
    const float* ego_q = (const float*)d_in[0];
    const float* nbr   = (const float*)d_in[1];
    const int*   mask  = (const int*)  d_in[2];
    const float* lnq_s = (const float*)d_in[3];
    const float* lnq_b = (const float*)d_in[4];
    const float* lnk_s = (const float*)d_in[5];
    const float* lnk_b = (const float*)d_in[6];
    const float* Wq    = (const float*)d_in[7];
    const float* bq    = (const float*)d_in[8];
    const float* Wk    = (const float*)d_in[9];
    const float* bk    = (const float*)d_in[10];
    const float* Wv    = (const float*)d_in[11];
    const float* bv    = (const float*)d_in[12];
    const float* Wo    = (const float*)d_in[13];
    const float* bo    = (const float*)d_in[14];
    float* y = (float*)d_out;

    const int BN = in_sizes[0] / Dm;  // B*N rows

    const size_t shmem =
        (size_t)(Dm + Dm * KT + 2 * Kn * PAD + Dm + Dm) * sizeof(float); // 52992 B

    cudaFuncSetAttribute(ego_attn_kernel,
                         cudaFuncAttributeMaxDynamicSharedMemorySize, (int)shmem);

    ego_attn_kernel<<<BN, 128, shmem>>>(
        ego_q, nbr, mask,
        lnq_s, lnq_b, lnk_s, lnk_b,
        Wq, bq, Wk, bk, Wv, bv, Wo, bo, y);
}

// round 16
// speedup vs baseline: 1.4397x; 1.4397x over previous
#include <cuda_runtime.h>
#include <math.h>

// EgoCrossAttnPool: B=8, N=2048, K=32, D=128, H=4, HD=32.
// One CTA of 128 threads per BN row, fp32 FFMA2 (fma.rn.f32x2) throughout.
// R16 (= R14/R15 resubmit; broker timed out). Fixes R13's rel_err=1.74: kh/vh
// row stride 33 < 128-col row length made rows overlap. kh/vh are now
// COLUMN-MAJOR with stride KS=33 (kh_t[c*KS + k]): correct by construction,
// conflict-free in both read phases (score: lane=k stride-1; attn-out:
// lane=d stride-33==1 mod 32). Keeps the 2D register tile (4k x 4col x {K,V})
// K/V projection: 3 memory ops per i (2x weight LDG.128 pre-packed + 1x
// full-width LDS.128) vs 16 FFMA2 — the fix for R3's l1tex 80.9% binder.
// smem 53.8KB -> 4 CTAs/SM; reg cap 128 -> hot loop unroll 4.

#define Dm   128
#define Kn   32
#define NH   4
#define HDm  32
#define KS   33    // kh/vh COLUMN stride (floats): 32 k-values + 1 pad
#define KT   36    // transposed kv stride (floats): 36*4=144 B ≡ 0 mod 16

typedef unsigned long long u64;

__device__ __forceinline__ u64 pack2(float lo, float hi) {
    u64 r;
    asm("mov.b64 %0, {%1, %2};" : "=l"(r) : "f"(lo), "f"(hi));
    return r;
}
__device__ __forceinline__ float2 unpack2(u64 v) {
    float2 f;
    asm("mov.b64 {%0, %1}, %2;" : "=f"(f.x), "=f"(f.y) : "l"(v));
    return f;
}
__device__ __forceinline__ u64 fma2(u64 a, u64 b, u64 c) {
    u64 d;
    asm("fma.rn.f32x2 %0, %1, %2, %3;" : "=l"(d) : "l"(a), "l"(b), "l"(c));
    return d;
}

__global__ __launch_bounds__(128, 4)
void ego_attn_kernel(
    const float* __restrict__ ego_q,
    const float* __restrict__ nbr,
    const int*   __restrict__ mask,
    const float* __restrict__ lnq_s, const float* __restrict__ lnq_b,
    const float* __restrict__ lnk_s, const float* __restrict__ lnk_b,
    const float* __restrict__ Wq, const float* __restrict__ bq,
    const float* __restrict__ Wk, const float* __restrict__ bk,
    const float* __restrict__ Wv, const float* __restrict__ bv,
    const float* __restrict__ Wo, const float* __restrict__ bo,
    float* __restrict__ y)
{
    extern __shared__ float smf[];
    float* q_sh  = smf;                   // 128
    float* kv_t  = q_sh  + Dm;            // 128*36 transposed: kv_t[i*KT + k]
    float* kh_t  = kv_t + Dm * KT;        // 128*33 col-major: kh_t[c*KS + k]
    float* vh_t  = kh_t + Dm * KS;        // 128*33 col-major
    float* qh_sh = vh_t + Dm * KS;        // 128
    float* o_sh  = qh_sh + Dm;            // 128

    __shared__ float red[NH];
    __shared__ int   msk[Kn];
    __shared__ int   hasany;

    const int bn   = blockIdx.x;
    const int t    = threadIdx.x;
    const int lane = t & 31;
    const int w    = t >> 5;

    // ---- mask + fallback (warp 0) ----
    if (w == 0) {
        int mv = (mask[bn * Kn + lane] != 0);
        unsigned bal = __ballot_sync(0xffffffffu, mv);
        if (lane == 0) hasany = (bal != 0);
        msk[lane] = mv | ((lane == 0) & (bal == 0));
    }

    // ---- LayerNorm of ego_q row (block reduce over 128) ----
    float x_q = ego_q[(size_t)bn * Dm + t];
    {
        float s = x_q;
        #pragma unroll
        for (int o = 16; o; o >>= 1) s += __shfl_xor_sync(0xffffffffu, s, o);
        if (lane == 0) red[w] = s;
        __syncthreads();
        float mu = (red[0] + red[1] + red[2] + red[3]) * (1.0f / Dm);
        float dx = x_q - mu;
        float v  = dx * dx;
        __syncthreads();   // all have read red before reuse
        #pragma unroll
        for (int o = 16; o; o >>= 1) v += __shfl_xor_sync(0xffffffffu, v, o);
        if (lane == 0) red[w] = v;
        __syncthreads();
        float var = (red[0] + red[1] + red[2] + red[3]) * (1.0f / Dm);
        q_sh[t] = dx * rsqrtf(var + 1e-6f) * lnq_s[t] + lnq_b[t];
    }

    // ---- LayerNorm of kv rows into TRANSPOSED smem: warp w -> rows [8w,8w+8) ----
    {
        float s0 = lnk_s[lane],      s1 = lnk_s[lane + 32],
              s2 = lnk_s[lane + 64], s3 = lnk_s[lane + 96];
        float b0 = lnk_b[lane],      b1 = lnk_b[lane + 32],
              b2 = lnk_b[lane + 64], b3 = lnk_b[lane + 96];
        for (int r = 0; r < 8; r++) {
            int row = w * 8 + r;
            const float* p = nbr + ((size_t)bn * Kn + row) * Dm;
            float x0 = p[lane], x1 = p[lane + 32], x2 = p[lane + 64], x3 = p[lane + 96];
            float s = x0 + x1 + x2 + x3;
            #pragma unroll
            for (int o = 16; o; o >>= 1) s += __shfl_xor_sync(0xffffffffu, s, o);
            float mu = s * (1.0f / Dm);
            float d0 = x0 - mu, d1 = x1 - mu, d2 = x2 - mu, d3 = x3 - mu;
            float v = d0 * d0 + d1 * d1 + d2 * d2 + d3 * d3;
            #pragma unroll
            for (int o = 16; o; o >>= 1) v += __shfl_xor_sync(0xffffffffu, v, o);
            float rs = rsqrtf(v * (1.0f / Dm) + 1e-6f);
            kv_t[(lane)      * KT + row] = d0 * rs * s0 + b0;
            kv_t[(lane + 32) * KT + row] = d1 * rs * s1 + b1;
            kv_t[(lane + 64) * KT + row] = d2 * rs * s2 + b2;
            kv_t[(lane + 96) * KT + row] = d3 * rs * s3 + b3;
        }
    }
    __syncthreads();

    // ---- Q projection (FFMA2 along i): thread t computes column t ----
    {
        const float* wq = Wq + t;
        u64 acc2 = pack2(bq[t], 0.f);
        const u64* q2 = (const u64*)q_sh;
        #pragma unroll 4
        for (int i = 0; i < Dm / 2; i++) {
            u64 w2 = pack2(wq[(2 * i) * Dm], wq[(2 * i + 1) * Dm]);
            acc2 = fma2(q2[i], w2, acc2);
        }
        float2 a = unpack2(acc2);
        qh_sh[t] = (a.x + a.y) * 0.17677669529663689f;  // (q@Wq+bq)/sqrt(32)
    }

    // ---- K & V projections: 2D register tile 4k x 4col x {K,V} per thread ----
    // lane = kg*4 + cg : kg in 0..7 (k-group, k = 4kg..4kg+3), cg in 0..3.
    // Warp covers all 32 k x 16 cols; two passes over col-halves.
    {
        const int kg = lane >> 2;
        const int cg = lane & 3;
        const int k0 = kg * 4;
        const float* xp = kv_t + k0;

        #pragma unroll 1
        for (int pass = 0; pass < 2; pass++) {
            const int cb = pass * 64 + w * 16 + cg * 4;   // col base (mult of 4)
            u64 aK[4][2], aV[4][2];
            {
                u64 bkA = *(const u64*)(bk + cb);
                u64 bkB = *(const u64*)(bk + cb + 2);
                u64 bvA = *(const u64*)(bv + cb);
                u64 bvB = *(const u64*)(bv + cb + 2);
                #pragma unroll
                for (int k = 0; k < 4; k++) {
                    aK[k][0] = bkA; aK[k][1] = bkB;
                    aV[k][0] = bvA; aV[k][1] = bvB;
                }
            }
            const float* wkp = Wk + cb;
            const float* wvp = Wv + cb;
            #pragma unroll 4
            for (int i = 0; i < Dm; i++) {
                // weights: packed col-pairs straight from memory (no re-pack)
                ulonglong2 wk2 = *(const ulonglong2*)(wkp + i * Dm);
                ulonglong2 wv2 = *(const ulonglong2*)(wvp + i * Dm);
                // x: one full-width LDS.128 (8 distinct 16B addrs x4 bcast)
                float4 xf = *(const float4*)(xp + i * KT);
                u64 x0 = pack2(xf.x, xf.x);
                u64 x1 = pack2(xf.y, xf.y);
                u64 x2 = pack2(xf.z, xf.z);
                u64 x3 = pack2(xf.w, xf.w);
                aK[0][0] = fma2(x0, wk2.x, aK[0][0]);
                aK[0][1] = fma2(x0, wk2.y, aK[0][1]);
                aV[0][0] = fma2(x0, wv2.x, aV[0][0]);
                aV[0][1] = fma2(x0, wv2.y, aV[0][1]);
                aK[1][0] = fma2(x1, wk2.x, aK[1][0]);
                aK[1][1] = fma2(x1, wk2.y, aK[1][1]);
                aV[1][0] = fma2(x1, wv2.x, aV[1][0]);
                aV[1][1] = fma2(x1, wv2.y, aV[1][1]);
                aK[2][0] = fma2(x2, wk2.x, aK[2][0]);
                aK[2][1] = fma2(x2, wk2.y, aK[2][1]);
                aV[2][0] = fma2(x2, wv2.x, aV[2][0]);
                aV[2][1] = fma2(x2, wv2.y, aV[2][1]);
                aK[3][0] = fma2(x3, wk2.x, aK[3][0]);
                aK[3][1] = fma2(x3, wk2.y, aK[3][1]);
                aV[3][0] = fma2(x3, wv2.x, aV[3][0]);
                aV[3][1] = fma2(x3, wv2.y, aV[3][1]);
            }
            // COLUMN-MAJOR stores: kh_t[c*KS + k]. Row k0+k, cols cb..cb+3.
            #pragma unroll
            for (int k = 0; k < 4; k++) {
                float2 kA = unpack2(aK[k][0]);
                float2 kB = unpack2(aK[k][1]);
                float2 vA = unpack2(aV[k][0]);
                float2 vB = unpack2(aV[k][1]);
                int kr = k0 + k;
                kh_t[(cb + 0) * KS + kr] = kA.x;
                kh_t[(cb + 1) * KS + kr] = kA.y;
                kh_t[(cb + 2) * KS + kr] = kB.x;
                kh_t[(cb + 3) * KS + kr] = kB.y;
                vh_t[(cb + 0) * KS + kr] = vA.x;
                vh_t[(cb + 1) * KS + kr] = vA.y;
                vh_t[(cb + 2) * KS + kr] = vB.x;
                vh_t[(cb + 3) * KS + kr] = vB.y;
            }
        }
    }
    __syncthreads();

    // ---- scores + masked softmax: warp w = head h, lane = k ----
    float attn;
    {
        const int h = w, k = lane;
        const float* qv = qh_sh + h * HDm;              // broadcast
        const float* kr = kh_t + (h * HDm) * KS + k;    // lane=k: stride-1 -> conflict-free
        float s = 0.f;
        #pragma unroll
        for (int d = 0; d < HDm; d++) s = fmaf(qv[d], kr[d * KS], s);
        float sm = msk[k] ? s : -3.0e38f;
        float mx = sm;
        #pragma unroll
        for (int o = 16; o; o >>= 1) mx = fmaxf(mx, __shfl_xor_sync(0xffffffffu, mx, o));
        float e = expf(sm - mx);
        float se = e;
        #pragma unroll
        for (int o = 16; o; o >>= 1) se += __shfl_xor_sync(0xffffffffu, se, o);
        attn = e / se;
    }

    // ---- out[h][d] = sum_k attn[h][k]*vh[k][h*32+d]; thread t = h*32+d ----
    {
        const int h = w, d = lane;
        const float* vp = vh_t + (h * HDm + d) * KS;    // lane=d: stride 33 == 1 mod 32
        float o = 0.f;
        #pragma unroll
        for (int k = 0; k < Kn; k++) {
            float a = __shfl_sync(0xffffffffu, attn, k);
            o = fmaf(a, vp[k], o);
        }
        o_sh[t] = o;
    }
    __syncthreads();

    // ---- output projection (FFMA2 along i) + has_any zeroing ----
    {
        const float* wo = Wo + t;
        u64 acc2 = pack2(bo[t], 0.f);
        const u64* o2 = (const u64*)o_sh;
        #pragma unroll 4
        for (int i = 0; i < Dm / 2; i++) {
            u64 w2 = pack2(wo[(2 * i) * Dm], wo[(2 * i + 1) * Dm]);
            acc2 = fma2(o2[i], w2, acc2);
        }
        float2 a = unpack2(acc2);
        float acc = a.x + a.y;
        if (!hasany) acc = 0.f;
        y[(size_t)bn * Dm + t] = acc;
    }
}

extern "C" void kernel_launch(void* const* d_in, const int* in_sizes, int n_in,
                              void* d_out, int out_size)
{
    const float* ego_q = (const float*)d_in[0];
    const float* nbr   = (const float*)d_in[1];
    const int*   mask  = (const int*)  d_in[2];
    const float* lnq_s = (const float*)d_in[3];
    const float* lnq_b = (const float*)d_in[4];
    const float* lnk_s = (const float*)d_in[5];
    const float* lnk_b = (const float*)d_in[6];
    const float* Wq    = (const float*)d_in[7];
    const float* bq    = (const float*)d_in[8];
    const float* Wk    = (const float*)d_in[9];
    const float* bk    = (const float*)d_in[10];
    const float* Wv    = (const float*)d_in[11];
    const float* bv    = (const float*)d_in[12];
    const float* Wo    = (const float*)d_in[13];
    const float* bo    = (const float*)d_in[14];
    float* y = (float*)d_out;

    const int BN = in_sizes[0] / Dm;  // B*N rows

    const size_t shmem =
        (size_t)(Dm + Dm * KT + 2 * Dm * KS + Dm + Dm) * sizeof(float); // 53760 B

    cudaFuncSetAttribute(ego_attn_kernel,
                         cudaFuncAttributeMaxDynamicSharedMemorySize, (int)shmem);

    ego_attn_kernel<<<BN, 128, shmem>>>(
        ego_q, nbr, mask,
        lnq_s, lnq_b, lnk_s, lnk_b,
        Wq, bq, Wk, bk, Wv, bv, Wo, bo, y);
}